// round 15
// baseline (speedup 1.0000x reference)
#include <cuda_runtime.h>
#include <cuda_bf16.h>
#include <cuda_fp16.h>

#define KDIM 8
static const int MAXN  = 100000;
static const int MAXNK = MAXN * KDIM;

// Scratch (device globals — no cudaMalloc allowed).
__device__ float4 g_accQ4[MAXNK];   // seeded es*q, then += ee * (rel x q_src)
__device__ float2 g_accDL2[MAXNK];  // seeded {es, es*l}, then += {ee, ee*l}
__device__ uint2  g_qph[MAXNK];     // half4-packed  max(l,2e-4)*q  (8B/(node,k))

// ---------------------------------------------------------------------------
// Prepass: half4 packed l*q table (norm encodes l) + self-term seeding.
// Self term uses exact fp32 l and q.
// ---------------------------------------------------------------------------
__global__ void __launch_bounds__(256)
spt_prep_kernel(const float* __restrict__ node_levels,
                const float4* __restrict__ node_q,
                int NK)
{
    int i = blockIdx.x * blockDim.x + threadIdx.x;
    if (i >= NK) return;
    float  l = node_levels[i];
    float4 q = node_q[i];

    float lc = fmaxf(l, 2e-4f);           // keep largest half comp normal-range
    __half2 h01 = __floats2half2_rn(lc * q.x, lc * q.y);
    __half2 h23 = __floats2half2_rn(lc * q.z, lc * q.w);
    uint2 packed;
    packed.x = *(unsigned int*)&h01;
    packed.y = *(unsigned int*)&h23;
    g_qph[i] = packed;

    float es = __expf(8.0f * l);          // self term; softmax shift cancels
    g_accQ4[i]  = make_float4(es * q.x, es * q.y, es * q.z, es * q.w);
    g_accDL2[i] = make_float2(es, es * l);
}

// ---------------------------------------------------------------------------
// Edge scatter: 2 (edge,k) elements per thread (t and t + halfEK).
// Single 8B gather per (edge,k): half4 qp = l*q; l = ||qp||, dir = qp/l.
// All loads issued up front; DL REDs issued before Hamilton FMAs.
// ---------------------------------------------------------------------------
__global__ void __launch_bounds__(256)
spt_edge_kernel(const float4* __restrict__ edge_rel_q,
                const float*  __restrict__ edge_w,
                const int*    __restrict__ edge_src,
                const int*    __restrict__ edge_dst,
                long long halfEK)
{
    long long t = (long long)blockIdx.x * blockDim.x + threadIdx.x;
    bool active = (t < halfEK);
    long long tc = active ? t : 0;        // clamp for safe loads
    long long u0 = tc;
    long long u1 = tc + halfEK;
    int e0 = (int)(u0 >> 3);
    int e1 = (int)(u1 >> 3);
    int k  = (int)(u0 & 7);               // same k for u1 (halfEK % 8 == 0)

    // ---- issue all loads up front ----
    int   s0 = __ldg(edge_src + e0);
    int   s1 = __ldg(edge_src + e1);
    int   d0 = __ldg(edge_dst + e0);
    int   d1 = __ldg(edge_dst + e1);
    float w0 = __ldg(edge_w + e0);
    float w1 = __ldg(edge_w + e1);
    float4 rq0 = __ldg(edge_rel_q + e0);
    float4 rq1 = __ldg(edge_rel_q + e1);
    uint2 qh0 = __ldg(g_qph + s0 * KDIM + k);   // 64B line per edge, 8 lanes
    uint2 qh1 = __ldg(g_qph + s1 * KDIM + k);

    // ---- unpack qp (fp16 -> fp32), recover l = ||qp|| ----
    float2 a01 = __half22float2(*(__half2*)&qh0.x);
    float2 a23 = __half22float2(*(__half2*)&qh0.y);
    float2 b01 = __half22float2(*(__half2*)&qh1.x);
    float2 b23 = __half22float2(*(__half2*)&qh1.y);

    float nq0   = a01.x*a01.x + a01.y*a01.y + a23.x*a23.x + a23.y*a23.y;
    float invl0 = rsqrtf(nq0);
    float l0    = nq0 * invl0;
    float nq1   = b01.x*b01.x + b01.y*b01.y + b23.x*b23.x + b23.y*b23.y;
    float invl1 = rsqrtf(nq1);
    float l1    = nq1 * invl1;

    // ---- softmax weights ----
    float ee0  = __expf(8.0f * w0 * l0);
    float eel0 = ee0 * l0;
    float ee1  = __expf(8.0f * w1 * l1);
    float eel1 = ee1 * l1;

    // ---- DL pairing via shfl (even lane k covers k and k+1) ----
    float nee0  = __shfl_down_sync(0xffffffffu, ee0,  1);
    float neel0 = __shfl_down_sync(0xffffffffu, eel0, 1);
    float nee1  = __shfl_down_sync(0xffffffffu, ee1,  1);
    float neel1 = __shfl_down_sync(0xffffffffu, eel1, 1);

    int di0 = d0 * KDIM + k;
    int di1 = d1 * KDIM + k;

    if (active && ((k & 1) == 0)) {
        float4* adl0 = (float4*)(g_accDL2 + di0);   // 16B aligned (di even)
        float4* adl1 = (float4*)(g_accDL2 + di1);
        asm volatile("red.global.add.v4.f32 [%0], {%1, %2, %3, %4};"
                     :: "l"(adl0), "f"(ee0), "f"(eel0), "f"(nee0), "f"(neel0)
                     : "memory");
        asm volatile("red.global.add.v4.f32 [%0], {%1, %2, %3, %4};"
                     :: "l"(adl1), "f"(ee1), "f"(eel1), "f"(nee1), "f"(neel1)
                     : "memory");
    }

    // ---- Hamilton products: (ee/l) * (rel_q x qp), storage (w,x,y,z) ----
    float sc0 = ee0 * invl0;
    float sc1 = ee1 * invl1;

    float aw0, ax0, ay0, az0;
    {
        float w1q = rq0.x, x1q = rq0.y, y1q = rq0.z, z1q = rq0.w;
        float w2q = a01.x, x2q = a01.y, y2q = a23.x, z2q = a23.y;
        aw0 = sc0 * (w1q*w2q - x1q*x2q - y1q*y2q - z1q*z2q);
        ax0 = sc0 * (w1q*x2q + x1q*w2q + y1q*z2q - z1q*y2q);
        ay0 = sc0 * (w1q*y2q - x1q*z2q + y1q*w2q + z1q*x2q);
        az0 = sc0 * (w1q*z2q + x1q*y2q - y1q*x2q + z1q*w2q);
    }
    float aw1, ax1, ay1, az1;
    {
        float w1q = rq1.x, x1q = rq1.y, y1q = rq1.z, z1q = rq1.w;
        float w2q = b01.x, x2q = b01.y, y2q = b23.x, z2q = b23.y;
        aw1 = sc1 * (w1q*w2q - x1q*x2q - y1q*y2q - z1q*z2q);
        ax1 = sc1 * (w1q*x2q + x1q*w2q + y1q*z2q - z1q*y2q);
        ay1 = sc1 * (w1q*y2q - x1q*z2q + y1q*w2q + z1q*x2q);
        az1 = sc1 * (w1q*z2q + x1q*y2q - y1q*x2q + z1q*w2q);
    }

    if (active) {
        float4* aq0 = g_accQ4 + di0;
        float4* aq1 = g_accQ4 + di1;
        asm volatile("red.global.add.v4.f32 [%0], {%1, %2, %3, %4};"
                     :: "l"(aq0), "f"(aw0), "f"(ax0), "f"(ay0), "f"(az0)
                     : "memory");
        asm volatile("red.global.add.v4.f32 [%0], {%1, %2, %3, %4};"
                     :: "l"(aq1), "f"(aw1), "f"(ax1), "f"(ay1), "f"(az1)
                     : "memory");
    }
}

// ---------------------------------------------------------------------------
// Finalize: normalize(a) (denom divide drops out of normalization);
// out_l = suml/denom.
// ---------------------------------------------------------------------------
__global__ void __launch_bounds__(256)
spt_final_kernel(float4* __restrict__ out_q,
                 float*  __restrict__ out_l,
                 int NK)
{
    int i = blockIdx.x * blockDim.x + threadIdx.x;
    if (i >= NK) return;

    float2 dl = g_accDL2[i];
    float4 a  = g_accQ4[i];

    float qq = a.x*a.x + a.y*a.y + a.z*a.z + a.w*a.w;
    float r  = rsqrtf(fmaxf(qq, 1e-24f));
    out_q[i] = make_float4(a.x * r, a.y * r, a.z * r, a.w * r);
    out_l[i] = __fdividef(dl.y, dl.x);
}

// ---------------------------------------------------------------------------
// Launch. Inputs: 0 node_levels [N,K], 1 node_q [N,K,4], 2 edge_rel_q [E,4],
//                 3 edge_w [E], 4 edge_src [E], 5 edge_dst [E].
// Output: q [N,K,4] flattened, then out_levels [N,K].
// ---------------------------------------------------------------------------
extern "C" void kernel_launch(void* const* d_in, const int* in_sizes, int n_in,
                              void* d_out, int out_size)
{
    const float*  node_levels = (const float*) d_in[0];
    const float4* node_q      = (const float4*)d_in[1];
    const float4* edge_rel_q  = (const float4*)d_in[2];
    const float*  edge_w      = (const float*) d_in[3];
    const int*    edge_src    = (const int*)   d_in[4];
    const int*    edge_dst    = (const int*)   d_in[5];

    int NK = in_sizes[0];                 // N*K
    int E  = in_sizes[3];
    long long EK = (long long)E * KDIM;
    long long halfEK = EK / 2;            // E even -> halfEK % 8 == 0

    float4* out_q = (float4*)d_out;
    float*  out_l = (float*)d_out + (long long)NK * 4;

    const int TPB = 256;
    int grid_nk = (NK + TPB - 1) / TPB;
    int grid_e2 = (int)((halfEK + TPB - 1) / TPB);

    spt_prep_kernel <<<grid_nk, TPB>>>(node_levels, node_q, NK);
    spt_edge_kernel <<<grid_e2, TPB>>>(edge_rel_q, edge_w, edge_src,
                                       edge_dst, halfEK);
    spt_final_kernel<<<grid_nk, TPB>>>(out_q, out_l, NK);
}

// round 16
// speedup vs baseline: 1.0462x; 1.0462x over previous
#include <cuda_runtime.h>
#include <cuda_bf16.h>
#include <cuda_fp16.h>

#define KDIM 8
static const int MAXN  = 100000;
static const int MAXNK = MAXN * KDIM;

// Scratch (device globals — no cudaMalloc allowed).
__device__ float4 g_accQ4[MAXNK];   // seeded es*q, then += ee * (rel x q_src)
__device__ float2 g_accDL2[MAXNK];  // seeded {es, es*l}, then += {ee, ee*l}
__device__ uint2  g_qh[MAXNK];      // half4-packed node_q (8B per (node,k))

// ---------------------------------------------------------------------------
// Prepass: half4 node table + self-term seeding (w=1 -> score 8*l).
// Self term uses exact fp32 l and q.
// ---------------------------------------------------------------------------
__global__ void __launch_bounds__(256)
spt_prep_kernel(const float* __restrict__ node_levels,
                const float4* __restrict__ node_q,
                int NK)
{
    int i = blockIdx.x * blockDim.x + threadIdx.x;
    if (i >= NK) return;
    float  l = node_levels[i];
    float4 q = node_q[i];

    __half2 h01 = __floats2half2_rn(q.x, q.y);
    __half2 h23 = __floats2half2_rn(q.z, q.w);
    uint2 packed;
    packed.x = *(unsigned int*)&h01;
    packed.y = *(unsigned int*)&h23;
    g_qh[i] = packed;

    float es = __expf(8.0f * l);          // self term; softmax shift cancels
    g_accQ4[i]  = make_float4(es * q.x, es * q.y, es * q.z, es * q.w);
    g_accDL2[i] = make_float2(es, es * l);
}

// ---------------------------------------------------------------------------
// Edge scatter: 2 (edge,k) elements per thread, t and t + halfEK.
// Gathers: half4 q (64B/edge) + fp32 l from input node_levels (32B/edge).
// l stays exact AND load-direct -> softmax weights exact and the DL REDs
// (dependent only on l,w) issue early, overlapping the Hamilton FMA chain.
// ---------------------------------------------------------------------------
__global__ void __launch_bounds__(256)
spt_edge_kernel(const float*  __restrict__ node_levels,
                const float4* __restrict__ edge_rel_q,
                const float*  __restrict__ edge_w,
                const int*    __restrict__ edge_src,
                const int*    __restrict__ edge_dst,
                long long halfEK)
{
    long long t = (long long)blockIdx.x * blockDim.x + threadIdx.x;
    bool active = (t < halfEK);
    long long tc = active ? t : 0;        // clamp for safe loads
    long long u0 = tc;
    long long u1 = tc + halfEK;
    int e0 = (int)(u0 >> 3);
    int e1 = (int)(u1 >> 3);
    int k  = (int)(u0 & 7);               // same k for u1 (halfEK % 8 == 0)

    // ---- issue all loads up front ----
    int   s0 = __ldg(edge_src + e0);
    int   s1 = __ldg(edge_src + e1);
    int   d0 = __ldg(edge_dst + e0);
    int   d1 = __ldg(edge_dst + e1);
    float w0 = __ldg(edge_w + e0);
    float w1 = __ldg(edge_w + e1);
    float4 rq0 = __ldg(edge_rel_q + e0);
    float4 rq1 = __ldg(edge_rel_q + e1);
    int si0 = s0 * KDIM + k;
    int si1 = s1 * KDIM + k;
    uint2 qh0 = __ldg(g_qh + si0);        // 64B line per edge across 8 lanes
    uint2 qh1 = __ldg(g_qh + si1);
    float l0  = __ldg(node_levels + si0); // 32B sector per edge (exact l)
    float l1  = __ldg(node_levels + si1);

    // ---- unpack q (fp16 -> fp32) ----
    float2 a01 = __half22float2(*(__half2*)&qh0.x);
    float2 a23 = __half22float2(*(__half2*)&qh0.y);
    float2 b01 = __half22float2(*(__half2*)&qh1.x);
    float2 b23 = __half22float2(*(__half2*)&qh1.y);

    // ---- softmax weights (exact fp32 l) ----
    float ee0  = __expf(8.0f * w0 * l0);
    float eel0 = ee0 * l0;
    float ee1  = __expf(8.0f * w1 * l1);
    float eel1 = ee1 * l1;

    // ---- DL pairing via shfl (even lane k covers k and k+1) ----
    float nee0  = __shfl_down_sync(0xffffffffu, ee0,  1);
    float neel0 = __shfl_down_sync(0xffffffffu, eel0, 1);
    float nee1  = __shfl_down_sync(0xffffffffu, ee1,  1);
    float neel1 = __shfl_down_sync(0xffffffffu, eel1, 1);

    int di0 = d0 * KDIM + k;
    int di1 = d1 * KDIM + k;

    if (active && ((k & 1) == 0)) {
        float4* adl0 = (float4*)(g_accDL2 + di0);   // 16B aligned (di even)
        float4* adl1 = (float4*)(g_accDL2 + di1);
        asm volatile("red.global.add.v4.f32 [%0], {%1, %2, %3, %4};"
                     :: "l"(adl0), "f"(ee0), "f"(eel0), "f"(nee0), "f"(neel0)
                     : "memory");
        asm volatile("red.global.add.v4.f32 [%0], {%1, %2, %3, %4};"
                     :: "l"(adl1), "f"(ee1), "f"(eel1), "f"(nee1), "f"(neel1)
                     : "memory");
    }

    // ---- Hamilton products: ee * (rel_q x q_src), storage (w,x,y,z) ----
    float aw0, ax0, ay0, az0;
    {
        float w1q = rq0.x, x1q = rq0.y, y1q = rq0.z, z1q = rq0.w;
        float w2q = a01.x, x2q = a01.y, y2q = a23.x, z2q = a23.y;
        aw0 = ee0 * (w1q*w2q - x1q*x2q - y1q*y2q - z1q*z2q);
        ax0 = ee0 * (w1q*x2q + x1q*w2q + y1q*z2q - z1q*y2q);
        ay0 = ee0 * (w1q*y2q - x1q*z2q + y1q*w2q + z1q*x2q);
        az0 = ee0 * (w1q*z2q + x1q*y2q - y1q*x2q + z1q*w2q);
    }
    float aw1, ax1, ay1, az1;
    {
        float w1q = rq1.x, x1q = rq1.y, y1q = rq1.z, z1q = rq1.w;
        float w2q = b01.x, x2q = b01.y, y2q = b23.x, z2q = b23.y;
        aw1 = ee1 * (w1q*w2q - x1q*x2q - y1q*y2q - z1q*z2q);
        ax1 = ee1 * (w1q*x2q + x1q*w2q + y1q*z2q - z1q*y2q);
        ay1 = ee1 * (w1q*y2q - x1q*z2q + y1q*w2q + z1q*x2q);
        az1 = ee1 * (w1q*z2q + x1q*y2q - y1q*x2q + z1q*w2q);
    }

    if (active) {
        float4* aq0 = g_accQ4 + di0;
        float4* aq1 = g_accQ4 + di1;
        asm volatile("red.global.add.v4.f32 [%0], {%1, %2, %3, %4};"
                     :: "l"(aq0), "f"(aw0), "f"(ax0), "f"(ay0), "f"(az0)
                     : "memory");
        asm volatile("red.global.add.v4.f32 [%0], {%1, %2, %3, %4};"
                     :: "l"(aq1), "f"(aw1), "f"(ax1), "f"(ay1), "f"(az1)
                     : "memory");
    }
}

// ---------------------------------------------------------------------------
// Finalize: normalize(a/denom) == normalize(a), so skip the denom divide on
// the quaternion entirely (eps clamp preserved on |a|). out_l = suml/denom.
// ---------------------------------------------------------------------------
__global__ void __launch_bounds__(256)
spt_final_kernel(float4* __restrict__ out_q,
                 float*  __restrict__ out_l,
                 int NK)
{
    int i = blockIdx.x * blockDim.x + threadIdx.x;
    if (i >= NK) return;

    float2 dl = g_accDL2[i];
    float4 a  = g_accQ4[i];

    float qq = a.x*a.x + a.y*a.y + a.z*a.z + a.w*a.w;
    float r  = rsqrtf(fmaxf(qq, 1e-24f));
    out_q[i] = make_float4(a.x * r, a.y * r, a.z * r, a.w * r);
    out_l[i] = __fdividef(dl.y, dl.x);
}

// ---------------------------------------------------------------------------
// Launch. Inputs: 0 node_levels [N,K], 1 node_q [N,K,4], 2 edge_rel_q [E,4],
//                 3 edge_w [E], 4 edge_src [E], 5 edge_dst [E].
// Output: q [N,K,4] flattened, then out_levels [N,K].
// ---------------------------------------------------------------------------
extern "C" void kernel_launch(void* const* d_in, const int* in_sizes, int n_in,
                              void* d_out, int out_size)
{
    const float*  node_levels = (const float*) d_in[0];
    const float4* node_q      = (const float4*)d_in[1];
    const float4* edge_rel_q  = (const float4*)d_in[2];
    const float*  edge_w      = (const float*) d_in[3];
    const int*    edge_src    = (const int*)   d_in[4];
    const int*    edge_dst    = (const int*)   d_in[5];

    int NK = in_sizes[0];                 // N*K
    int E  = in_sizes[3];
    long long EK = (long long)E * KDIM;
    long long halfEK = EK / 2;            // E even -> halfEK % 8 == 0

    float4* out_q = (float4*)d_out;
    float*  out_l = (float*)d_out + (long long)NK * 4;

    const int TPB = 256;
    int grid_nk = (NK + TPB - 1) / TPB;
    int grid_e2 = (int)((halfEK + TPB - 1) / TPB);

    spt_prep_kernel <<<grid_nk, TPB>>>(node_levels, node_q, NK);
    spt_edge_kernel <<<grid_e2, TPB>>>(node_levels, edge_rel_q, edge_w,
                                       edge_src, edge_dst, halfEK);
    spt_final_kernel<<<grid_nk, TPB>>>(out_q, out_l, NK);
}

// round 17
// speedup vs baseline: 1.0544x; 1.0078x over previous
#include <cuda_runtime.h>
#include <cuda_bf16.h>
#include <cuda_fp16.h>

#define KDIM 8
static const int MAXN  = 100000;
static const int MAXNK = MAXN * KDIM;

// Scratch (device globals — no cudaMalloc allowed).
__device__ float4 g_accQ4[MAXNK];   // seeded es*q, then += ee * (rel x q_src)
__device__ float2 g_accDL2[MAXNK];  // seeded {es, es*l}, then += {ee, ee*l}
__device__ uint2  g_qh[MAXNK];      // half4-packed node_q (8B per (node,k))

// ---------------------------------------------------------------------------
// Prepass: half4 node table + self-term seeding (w=1 -> score 8*l).
// Self term uses exact fp32 l and q.
// ---------------------------------------------------------------------------
__global__ void __launch_bounds__(256)
spt_prep_kernel(const float* __restrict__ node_levels,
                const float4* __restrict__ node_q,
                int NK)
{
    int i = blockIdx.x * blockDim.x + threadIdx.x;
    if (i >= NK) return;
    float  l = node_levels[i];
    float4 q = node_q[i];

    __half2 h01 = __floats2half2_rn(q.x, q.y);
    __half2 h23 = __floats2half2_rn(q.z, q.w);
    uint2 packed;
    packed.x = *(unsigned int*)&h01;
    packed.y = *(unsigned int*)&h23;
    g_qh[i] = packed;

    float es = __expf(8.0f * l);          // self term; softmax shift cancels
    g_accQ4[i]  = make_float4(es * q.x, es * q.y, es * q.z, es * q.w);
    g_accDL2[i] = make_float2(es, es * l);
}

// ---------------------------------------------------------------------------
// Edge scatter: 2 (edge,k) elements per thread, t and t + halfEK.
// Edge-stream arrays (read exactly once) use __ldcs (evict-first) so they
// don't churn L2 residency of the hot accumulators + node tables.
// Gathers: half4 q (64B/edge) + fp32 l (32B/edge, exact, load-direct so the
// DL REDs issue early, overlapping the Hamilton FMA chain).
// ---------------------------------------------------------------------------
__global__ void __launch_bounds__(256)
spt_edge_kernel(const float*  __restrict__ node_levels,
                const float4* __restrict__ edge_rel_q,
                const float*  __restrict__ edge_w,
                const int*    __restrict__ edge_src,
                const int*    __restrict__ edge_dst,
                long long halfEK)
{
    long long t = (long long)blockIdx.x * blockDim.x + threadIdx.x;
    bool active = (t < halfEK);
    long long tc = active ? t : 0;        // clamp for safe loads
    long long u0 = tc;
    long long u1 = tc + halfEK;
    int e0 = (int)(u0 >> 3);
    int e1 = (int)(u1 >> 3);
    int k  = (int)(u0 & 7);               // same k for u1 (halfEK % 8 == 0)

    // ---- issue all loads up front (stream: evict-first) ----
    int   s0 = __ldcs(edge_src + e0);
    int   s1 = __ldcs(edge_src + e1);
    int   d0 = __ldcs(edge_dst + e0);
    int   d1 = __ldcs(edge_dst + e1);
    float w0 = __ldcs(edge_w + e0);
    float w1 = __ldcs(edge_w + e1);
    float4 rq0 = __ldcs(edge_rel_q + e0);
    float4 rq1 = __ldcs(edge_rel_q + e1);
    int si0 = s0 * KDIM + k;
    int si1 = s1 * KDIM + k;
    uint2 qh0 = __ldg(g_qh + si0);        // hot table: default policy
    uint2 qh1 = __ldg(g_qh + si1);
    float l0  = __ldg(node_levels + si0); // hot table: default policy
    float l1  = __ldg(node_levels + si1);

    // ---- unpack q (fp16 -> fp32) ----
    float2 a01 = __half22float2(*(__half2*)&qh0.x);
    float2 a23 = __half22float2(*(__half2*)&qh0.y);
    float2 b01 = __half22float2(*(__half2*)&qh1.x);
    float2 b23 = __half22float2(*(__half2*)&qh1.y);

    // ---- softmax weights (exact fp32 l) ----
    float ee0  = __expf(8.0f * w0 * l0);
    float eel0 = ee0 * l0;
    float ee1  = __expf(8.0f * w1 * l1);
    float eel1 = ee1 * l1;

    // ---- DL pairing via shfl (even lane k covers k and k+1) ----
    float nee0  = __shfl_down_sync(0xffffffffu, ee0,  1);
    float neel0 = __shfl_down_sync(0xffffffffu, eel0, 1);
    float nee1  = __shfl_down_sync(0xffffffffu, ee1,  1);
    float neel1 = __shfl_down_sync(0xffffffffu, eel1, 1);

    int di0 = d0 * KDIM + k;
    int di1 = d1 * KDIM + k;

    if (active && ((k & 1) == 0)) {
        float4* adl0 = (float4*)(g_accDL2 + di0);   // 16B aligned (di even)
        float4* adl1 = (float4*)(g_accDL2 + di1);
        asm volatile("red.global.add.v4.f32 [%0], {%1, %2, %3, %4};"
                     :: "l"(adl0), "f"(ee0), "f"(eel0), "f"(nee0), "f"(neel0)
                     : "memory");
        asm volatile("red.global.add.v4.f32 [%0], {%1, %2, %3, %4};"
                     :: "l"(adl1), "f"(ee1), "f"(eel1), "f"(nee1), "f"(neel1)
                     : "memory");
    }

    // ---- Hamilton products: ee * (rel_q x q_src), storage (w,x,y,z) ----
    float aw0, ax0, ay0, az0;
    {
        float w1q = rq0.x, x1q = rq0.y, y1q = rq0.z, z1q = rq0.w;
        float w2q = a01.x, x2q = a01.y, y2q = a23.x, z2q = a23.y;
        aw0 = ee0 * (w1q*w2q - x1q*x2q - y1q*y2q - z1q*z2q);
        ax0 = ee0 * (w1q*x2q + x1q*w2q + y1q*z2q - z1q*y2q);
        ay0 = ee0 * (w1q*y2q - x1q*z2q + y1q*w2q + z1q*x2q);
        az0 = ee0 * (w1q*z2q + x1q*y2q - y1q*x2q + z1q*w2q);
    }
    float aw1, ax1, ay1, az1;
    {
        float w1q = rq1.x, x1q = rq1.y, y1q = rq1.z, z1q = rq1.w;
        float w2q = b01.x, x2q = b01.y, y2q = b23.x, z2q = b23.y;
        aw1 = ee1 * (w1q*w2q - x1q*x2q - y1q*y2q - z1q*z2q);
        ax1 = ee1 * (w1q*x2q + x1q*w2q + y1q*z2q - z1q*y2q);
        ay1 = ee1 * (w1q*y2q - x1q*z2q + y1q*w2q + z1q*x2q);
        az1 = ee1 * (w1q*z2q + x1q*y2q - y1q*x2q + z1q*w2q);
    }

    if (active) {
        float4* aq0 = g_accQ4 + di0;
        float4* aq1 = g_accQ4 + di1;
        asm volatile("red.global.add.v4.f32 [%0], {%1, %2, %3, %4};"
                     :: "l"(aq0), "f"(aw0), "f"(ax0), "f"(ay0), "f"(az0)
                     : "memory");
        asm volatile("red.global.add.v4.f32 [%0], {%1, %2, %3, %4};"
                     :: "l"(aq1), "f"(aw1), "f"(ax1), "f"(ay1), "f"(az1)
                     : "memory");
    }
}

// ---------------------------------------------------------------------------
// Finalize: normalize(a/denom) == normalize(a), so skip the denom divide on
// the quaternion entirely (eps clamp preserved on |a|). out_l = suml/denom.
// ---------------------------------------------------------------------------
__global__ void __launch_bounds__(256)
spt_final_kernel(float4* __restrict__ out_q,
                 float*  __restrict__ out_l,
                 int NK)
{
    int i = blockIdx.x * blockDim.x + threadIdx.x;
    if (i >= NK) return;

    float2 dl = g_accDL2[i];
    float4 a  = g_accQ4[i];

    float qq = a.x*a.x + a.y*a.y + a.z*a.z + a.w*a.w;
    float r  = rsqrtf(fmaxf(qq, 1e-24f));
    out_q[i] = make_float4(a.x * r, a.y * r, a.z * r, a.w * r);
    out_l[i] = __fdividef(dl.y, dl.x);
}

// ---------------------------------------------------------------------------
// Launch. Inputs: 0 node_levels [N,K], 1 node_q [N,K,4], 2 edge_rel_q [E,4],
//                 3 edge_w [E], 4 edge_src [E], 5 edge_dst [E].
// Output: q [N,K,4] flattened, then out_levels [N,K].
// ---------------------------------------------------------------------------
extern "C" void kernel_launch(void* const* d_in, const int* in_sizes, int n_in,
                              void* d_out, int out_size)
{
    const float*  node_levels = (const float*) d_in[0];
    const float4* node_q      = (const float4*)d_in[1];
    const float4* edge_rel_q  = (const float4*)d_in[2];
    const float*  edge_w      = (const float*) d_in[3];
    const int*    edge_src    = (const int*)   d_in[4];
    const int*    edge_dst    = (const int*)   d_in[5];

    int NK = in_sizes[0];                 // N*K
    int E  = in_sizes[3];
    long long EK = (long long)E * KDIM;
    long long halfEK = EK / 2;            // E even -> halfEK % 8 == 0

    float4* out_q = (float4*)d_out;
    float*  out_l = (float*)d_out + (long long)NK * 4;

    const int TPB = 256;
    int grid_nk = (NK + TPB - 1) / TPB;
    int grid_e2 = (int)((halfEK + TPB - 1) / TPB);

    spt_prep_kernel <<<grid_nk, TPB>>>(node_levels, node_q, NK);
    spt_edge_kernel <<<grid_e2, TPB>>>(node_levels, edge_rel_q, edge_w,
                                       edge_src, edge_dst, halfEK);
    spt_final_kernel<<<grid_nk, TPB>>>(out_q, out_l, NK);
}